// round 7
// baseline (speedup 1.0000x reference)
#include <cuda_runtime.h>
#include <cuda_bf16.h>
#include <math.h>

#define EMB 64
#define RNN 128
#define BB  512
#define LL  256
#define KK  18
#define G   8
#define ZC  512   // 4*RNN
#define VOCAB 30001
#define PG  16    // vocab rows per pbuild block
#define LR  28    // (b,t) rows per logits block

// Scratch (static device allocations; no cudaMalloc allowed)
// g_P: bf16x2-packed, GATE-INTERLEAVED permuted columns: perm col n -> unit n>>2, gate n&3
__device__ unsigned int g_P[2][VOCAB][ZC / 2];   // ~61 MB total (L2-resident)
__device__ float g_hcat[LL][BB][2 * RNN];        // concat(h_fwd, h_bwd)
__device__ float g_logits[BB][LL][KK];

typedef unsigned long long u64;
typedef unsigned int u32;

__device__ __forceinline__ u64 pk2(float lo, float hi) {
    u64 r; asm("mov.b64 %0,{%1,%2};" : "=l"(r) : "f"(lo), "f"(hi)); return r;
}
__device__ __forceinline__ void upk2(u64 v, float& lo, float& hi) {
    asm("mov.b64 {%0,%1},%2;" : "=f"(lo), "=f"(hi) : "l"(v));
}
__device__ __forceinline__ void ffma2(u64& d, u64 a, u64 b) {
    asm("fma.rn.f32x2 %0,%1,%2,%0;" : "+l"(d) : "l"(a), "l"(b));
}
__device__ __forceinline__ float fast_tanh(float x) {
    float y; asm("tanh.approx.f32 %0, %1;" : "=f"(y) : "f"(x)); return y;
}
__device__ __forceinline__ float fast_sig(float x) {
    return 0.5f * fast_tanh(0.5f * x) + 0.5f;
}
__device__ __forceinline__ u32 pack_bf16(float lo, float hi) {
    __nv_bfloat162 v = __floats2bfloat162_rn(lo, hi);
    return *(u32*)&v;
}
__device__ __forceinline__ float2 unpack_bf16(u32 v) {
    __nv_bfloat162 b = *(__nv_bfloat162*)&v;
    return make_float2(__bfloat162float(b.x), __bfloat162float(b.y));
}
__device__ __forceinline__ void mma16816(float& d0, float& d1, float& d2, float& d3,
                                         u32 a0, u32 a1, u32 a2, u32 a3,
                                         u32 b0, u32 b1) {
    asm("mma.sync.aligned.m16n8k16.row.col.f32.bf16.bf16.f32 "
        "{%0,%1,%2,%3}, {%4,%5,%6,%7}, {%8,%9}, {%0,%1,%2,%3};"
        : "+f"(d0), "+f"(d1), "+f"(d2), "+f"(d3)
        : "r"(a0), "r"(a1), "r"(a2), "r"(a3), "r"(b0), "r"(b1));
}

// ---------------------------------------------------------------------------
// Kernel 1: P[dir][v][perm] = bf16( E[v] @ Wx_dir + b_dir )  (vocab factoring,
// gate-interleaved permuted + bf16x2 packed output)
// ---------------------------------------------------------------------------
__global__ __launch_bounds__(512) void pbuild_kernel(
    const float* __restrict__ E,
    const float* __restrict__ Wx_f, const float* __restrict__ b_f,
    const float* __restrict__ Wx_b, const float* __restrict__ b_b)
{
    int dir = blockIdx.y;
    int r0  = blockIdx.x * PG;
    const float* __restrict__ Wx = dir ? Wx_b : Wx_f;
    const float* __restrict__ bs = dir ? b_b : b_f;

    __shared__ __align__(16) float x_s[EMB][PG];
    __shared__ float ps[PG][ZC];     // fp32 results in ORIGINAL column order
    int tid = threadIdx.x;
    for (int i = tid; i < PG * EMB; i += 512) {
        int r = i & (PG - 1), e = i / PG;
        int row = r0 + r;
        x_s[e][r] = (row < VOCAB) ? E[row * EMB + e] : 0.0f;
    }
    __syncthreads();

    float bv = bs[tid];
    u64 bp = pk2(bv, bv);
    u64 acc[PG / 2];
#pragma unroll
    for (int p = 0; p < PG / 2; p++) acc[p] = bp;

    const float* wc = Wx + tid;
#pragma unroll 4
    for (int e = 0; e < EMB; e++) {
        float w = wc[e * ZC];
        u64 wd = pk2(w, w);
        const u64* xp = (const u64*)&x_s[e][0];
#pragma unroll
        for (int p = 0; p < PG / 2; p++) ffma2(acc[p], wd, xp[p]);
    }
#pragma unroll
    for (int p = 0; p < PG / 2; p++) {
        float lo, hi; upk2(acc[p], lo, hi);
        ps[2 * p][tid] = lo;
        ps[2 * p + 1][tid] = hi;
    }
    __syncthreads();

    // pack to permuted bf16x2: pair p covers perm cols (2p,2p+1) ->
    // orig cols c_lo = 2(p&1)*128 + (p>>1), c_hi = c_lo + 128
    for (int i = tid; i < PG * (ZC / 2); i += 512) {
        int r = i >> 8, p = i & 255;
        int c_lo = ((p & 1) * 2) * 128 + (p >> 1);
        int row = r0 + r;
        if (row < VOCAB)
            g_P[dir][row][p] = pack_bf16(ps[r][c_lo], ps[r][c_lo + 128]);
    }
}

// ---------------------------------------------------------------------------
// Kernel 2: persistent LSTM via mma.sync m16n8k16 bf16, gate-interleaved cols.
// 128 blocks = 2 dirs x 64 batch-groups. Wh bf16 fragments in registers;
// h in double-buffered fragment-layout smem; 1 barrier/step; warp-local epilogue.
// ---------------------------------------------------------------------------
__global__ __launch_bounds__(512, 1) void lstm_kernel(
    const int* __restrict__ inputs,
    const float* __restrict__ Wh_f, const float* __restrict__ Wh_b)
{
    __shared__ __align__(16) u32 hA[8 * 128];   // 4KB each: 8 k-chunks x 32 lanes x 16B
    __shared__ __align__(16) u32 hB[8 * 128];
    __shared__ int tok_s[G][LL];

    int dir = blockIdx.x >> 6;
    int bi  = blockIdx.x & 63;
    int b0  = bi * G;
    const float* __restrict__ Wh = dir ? Wh_b : Wh_f;
    int tid  = threadIdx.x;
    int w    = tid >> 5;       // warp 0..15: perm cols [32w, 32w+32) = units [8w, 8w+8)
    int lane = tid & 31;
    int gm   = lane >> 2;      // batch row (0..7) / B-frag col / D-frag row
    int tl   = lane & 3;       // k/col pair selector

    for (int i = tid; i < 8 * 128; i += 512) { hA[i] = 0u; hB[i] = 0u; }
    for (int i = tid; i < G * LL; i += 512) {
        int g = i >> 8, t = i & 255;
        tok_s[g][t] = inputs[(b0 + g) * LL + t];
    }

    // Wh -> bf16 B fragments (perm cols): n = 32w+8nt+gm, orig col o = (n&3)*128 + (n>>2)
    u32 bfr[4][8][2];
#pragma unroll
    for (int nt = 0; nt < 4; nt++) {
        int n = w * 32 + nt * 8 + gm;
        int o = (n & 3) * 128 + (n >> 2);
#pragma unroll
        for (int kc = 0; kc < 8; kc++) {
            int kb = 16 * kc + 2 * tl;
            bfr[nt][kc][0] = pack_bf16(Wh[kb * ZC + o],       Wh[(kb + 1) * ZC + o]);
            bfr[nt][kc][1] = pack_bf16(Wh[(kb + 8) * ZC + o], Wh[(kb + 9) * ZC + o]);
        }
    }
    __syncthreads();

    // P prefetch (bf16x2), one step ahead: pair idx = 16w + 4nt + tl
    int t0 = dir ? (LL - 1) : 0;
    u32 pf[4];
#pragma unroll
    for (int nt = 0; nt < 4; nt++)
        pf[nt] = g_P[dir][tok_s[gm][t0]][w * 16 + nt * 4 + tl];

    int myNt0 = (tl & 1) ? 2 : 0;   // which nt tiles this lane's cells come from
    float cst[2] = {0.0f, 0.0f};

    for (int step = 0; step < LL; step++) {
        int t = dir ? (LL - 1 - step) : step;
        const u32* rd = (step & 1) ? hB : hA;
        __nv_bfloat16* wr = (__nv_bfloat16*)((step & 1) ? hA : hB);

        float d0[4], d1[4], d2[4], d3[4];
#pragma unroll
        for (int nt = 0; nt < 4; nt++) {
            float2 pv = unpack_bf16(pf[nt]);
            d0[nt] = pv.x; d1[nt] = pv.y; d2[nt] = 0.0f; d3[nt] = 0.0f;
        }

        int tn = (step + 1 < LL) ? (dir ? t - 1 : t + 1) : t;
#pragma unroll
        for (int nt = 0; nt < 4; nt++)
            pf[nt] = g_P[dir][tok_s[gm][tn]][w * 16 + nt * 4 + tl];

#pragma unroll
        for (int kc = 0; kc < 8; kc++) {
            uint4 af = *(const uint4*)&rd[(kc * 512 + lane * 16) >> 2];
#pragma unroll
            for (int nt = 0; nt < 4; nt++)
                mma16816(d0[nt], d1[nt], d2[nt], d3[nt],
                         af.x, af.y, af.z, af.w,
                         bfr[nt][kc][0], bfr[nt][kc][1]);
        }

        // warp-local epilogue: lane pair (xor 1) exchange -> each lane gets
        // all 4 gates for 2 cells (rows gm, units 8w + 2nt' + (tl>>1))
        u64 zown[4], zpart[4];
#pragma unroll
        for (int nt = 0; nt < 4; nt++) {
            zown[nt] = pk2(d0[nt], d1[nt]);
            zpart[nt] = __shfl_xor_sync(0xffffffffu, zown[nt], 1);
        }
#pragma unroll
        for (int j = 0; j < 2; j++) {
            int ntp = myNt0 + j;
            u64 zif = (tl & 1) ? zpart[ntp] : zown[ntp];
            u64 zgo = (tl & 1) ? zown[ntp] : zpart[ntp];
            float iz, fz; upk2(zif, iz, fz);
            float gz, oz; upk2(zgo, gz, oz);
            float c = fast_sig(fz) * cst[j] + fast_sig(iz) * fast_tanh(gz);
            cst[j] = c;
            float h = fast_sig(oz) * fast_tanh(c);

            int u = 8 * w + 2 * ntp + (tl >> 1);
            int kc = u >> 4, cc = u & 15;
            int tig = (cc >> 1) & 3, off8 = cc & 8, half = cc & 1;
            wr[((kc * 512 + (4 * gm + tig) * 16 + off8) >> 1) + half] = __float2bfloat16(h);
            g_hcat[t][b0 + gm][dir * RNN + u] = h;
        }
        __syncthreads();
    }
}

// ---------------------------------------------------------------------------
// Kernel 3: logits[b][t][k] = hcat[bt] . Wd[:,k] + bd[k]
// ---------------------------------------------------------------------------
__global__ __launch_bounds__(512) void logits_kernel(
    const float* __restrict__ Wd, const float* __restrict__ bd)
{
    __shared__ __align__(16) float h_s[LR][2 * RNN];
    __shared__ __align__(16) float2 Wt2[KK][RNN + 1];
    __shared__ float bd_s[KK];

    int tid = threadIdx.x;
    int bt0 = blockIdx.x * LR;

    for (int i = tid; i < KK * RNN; i += 512) {
        int k = i / RNN, e2 = i % RNN;
        Wt2[k][e2] = make_float2(Wd[(2 * e2) * KK + k], Wd[(2 * e2 + 1) * KK + k]);
    }
    if (tid < KK) bd_s[tid] = bd[tid];
    for (int i = tid; i < LR * 2 * RNN; i += 512) {
        int r = i >> 8, e = i & 255;
        int bt = bt0 + r;
        if (bt < BB * LL) {
            int b = bt >> 8, t = bt & 255;
            h_s[r][e] = g_hcat[t][b][e];
        }
    }
    __syncthreads();

    if (tid >= LR * KK) return;
    int r = tid / KK, k = tid % KK;
    int bt = bt0 + r;
    if (bt >= BB * LL) return;

    u64 acc = 0;
    const u64* hp = (const u64*)&h_s[r][0];
    const u64* wp = (const u64*)&Wt2[k][0];
#pragma unroll 8
    for (int e2 = 0; e2 < RNN; e2++) ffma2(acc, hp[e2], wp[e2]);

    float lo, hi; upk2(acc, lo, hi);
    int b = bt >> 8, t = bt & 255;
    g_logits[b][t][k] = lo + hi + bd_s[k];
}

// ---------------------------------------------------------------------------
// Kernel 4: CRF log-likelihood (+ fused T copy). expT trick: the recurrence
// alpha' = m + log(sum_k1 exp(alpha_k1 - m) * expT[k1][k]) + logit
// needs only 1 exp + 1 log per lane-step (expT precomputed, T in [0,1] safe).
// ---------------------------------------------------------------------------
__global__ __launch_bounds__(128) void crf_kernel(
    const int* __restrict__ labels, const float* __restrict__ T,
    float* __restrict__ out, int out_size)
{
    if (blockIdx.x == BB / 4) {
        for (int i = threadIdx.x; i < KK * KK; i += 128)
            if ((BB + i) < out_size) out[BB + i] = T[i];
        return;
    }

    __shared__ float T_s[KK * KK];
    __shared__ float expT_s[KK][KK];   // expT[k1][k]
    int tid = threadIdx.x;
    for (int i = tid; i < KK * KK; i += 128) {
        float tv = T[i];
        T_s[i] = tv;
        expT_s[i / KK][i % KK] = __expf(tv);
    }
    __syncthreads();

    int warp = tid >> 5;
    int lane = tid & 31;
    int b = blockIdx.x * 4 + warp;
    if (b >= BB) return;

    const int* lab = labels + b * LL;

    int cnt = 0;
    for (int l = lane; l < LL; l += 32) cnt += (lab[l] != 0);
#pragma unroll
    for (int off = 16; off; off >>= 1) cnt += __shfl_xor_sync(0xffffffffu, cnt, off);
    int len = cnt;

    float us = 0.0f, bs = 0.0f;
    for (int l = lane; l < LL; l += 32) {
        int y = lab[l];
        if (l < len) us += g_logits[b][l][y];
        if (l >= 1 && l < len) bs += T_s[lab[l - 1] * KK + y];
    }
#pragma unroll
    for (int off = 16; off; off >>= 1) {
        us += __shfl_xor_sync(0xffffffffu, us, off);
        bs += __shfl_xor_sync(0xffffffffu, bs, off);
    }

    int k = (lane < KK) ? lane : 0;
    float alpha = (lane < KK) ? g_logits[b][0][k] : -1e30f;
    for (int l = 1; l < LL; l++) {
        float m = alpha;
#pragma unroll
        for (int off = 16; off; off >>= 1) m = fmaxf(m, __shfl_xor_sync(0xffffffffu, m, off));
        float e = (lane < KK) ? __expf(alpha - m) : 0.0f;
        float s = 0.0f;
#pragma unroll
        for (int k1 = 0; k1 < KK; k1++)
            s = fmaf(__shfl_sync(0xffffffffu, e, k1), expT_s[k1][k], s);
        float na = m + __logf(s) + g_logits[b][l][k];
        if (lane < KK && l < len) alpha = na;
    }

    float m = alpha;
#pragma unroll
    for (int off = 16; off; off >>= 1) m = fmaxf(m, __shfl_xor_sync(0xffffffffu, m, off));
    float es = (lane < KK) ? __expf(alpha - m) : 0.0f;
#pragma unroll
    for (int off = 16; off; off >>= 1) es += __shfl_xor_sync(0xffffffffu, es, off);
    float lse = m + __logf(es);

    if (lane == 0 && b < out_size) out[b] = us + bs - lse;
}

// ---------------------------------------------------------------------------
extern "C" void kernel_launch(void* const* d_in, const int* in_sizes, int n_in,
                              void* d_out, int out_size)
{
    const int*   inputs = (const int*)  d_in[0];
    const int*   labels = (const int*)  d_in[1];
    const float* E      = (const float*)d_in[2];
    const float* Wx_f   = (const float*)d_in[3];
    const float* Wh_f   = (const float*)d_in[4];
    const float* b_f    = (const float*)d_in[5];
    const float* Wx_b   = (const float*)d_in[6];
    const float* Wh_b   = (const float*)d_in[7];
    const float* b_b    = (const float*)d_in[8];
    const float* Wd     = (const float*)d_in[9];
    const float* bd     = (const float*)d_in[10];
    const float* T      = (const float*)d_in[11];
    float* out = (float*)d_out;

    dim3 pg((VOCAB + PG - 1) / PG, 2);
    pbuild_kernel<<<pg, 512>>>(E, Wx_f, b_f, Wx_b, b_b);
    lstm_kernel<<<128, 512>>>(inputs, Wh_f, Wh_b);
    int nbt = BB * LL;
    logits_kernel<<<(nbt + LR - 1) / LR, 512>>>(Wd, bd);
    crf_kernel<<<BB / 4 + 1, 128>>>(labels, T, out, out_size);
}

// round 8
// speedup vs baseline: 1.3892x; 1.3892x over previous
#include <cuda_runtime.h>
#include <cuda_bf16.h>
#include <math.h>

#define EMB 64
#define RNN 128
#define BB  512
#define LL  256
#define KK  18
#define G   8
#define ZC  512   // 4*RNN
#define VOCAB 30001
#define PG  16    // vocab rows per pbuild block
#define LR  28    // (b,t) rows per logits block

// Scratch (static device allocations; no cudaMalloc allowed)
// g_P: bf16x2-packed, pair q holds permuted z-cols (p, p+8); perm col p:
//   warp w = p>>5, c = p&31, gate = c>>3, unit = 8w + (c&7); orig = gate*128+unit
__device__ unsigned int g_P[2][VOCAB][ZC / 2];        // ~61 MB (L2-resident)
// h staging: [dir][batch-group][t][tid] = bf16x2(h_even_batch, h_odd_batch)
__device__ unsigned int g_hstage[2][BB / G][LL][512]; // 67 MB, coalesced writes
__device__ float g_logits[BB][LL][KK];

typedef unsigned long long u64;
typedef unsigned int u32;

__device__ __forceinline__ u64 pk2(float lo, float hi) {
    u64 r; asm("mov.b64 %0,{%1,%2};" : "=l"(r) : "f"(lo), "f"(hi)); return r;
}
__device__ __forceinline__ void upk2(u64 v, float& lo, float& hi) {
    asm("mov.b64 {%0,%1},%2;" : "=f"(lo), "=f"(hi) : "l"(v));
}
__device__ __forceinline__ void ffma2(u64& d, u64 a, u64 b) {
    asm("fma.rn.f32x2 %0,%1,%2,%0;" : "+l"(d) : "l"(a), "l"(b));
}
__device__ __forceinline__ float fast_tanh(float x) {
    float y; asm("tanh.approx.f32 %0, %1;" : "=f"(y) : "f"(x)); return y;
}
__device__ __forceinline__ float fast_sig(float x) {
    return 0.5f * fast_tanh(0.5f * x) + 0.5f;
}
__device__ __forceinline__ u32 pack_bf16(float lo, float hi) {
    __nv_bfloat162 v = __floats2bfloat162_rn(lo, hi);
    return *(u32*)&v;
}
__device__ __forceinline__ float2 unpack_bf16(u32 v) {
    __nv_bfloat162 b = *(__nv_bfloat162*)&v;
    return make_float2(__bfloat162float(b.x), __bfloat162float(b.y));
}
__device__ __forceinline__ void mma16816(float& d0, float& d1, float& d2, float& d3,
                                         u32 a0, u32 a1, u32 a2, u32 a3,
                                         u32 b0, u32 b1) {
    asm("mma.sync.aligned.m16n8k16.row.col.f32.bf16.bf16.f32 "
        "{%0,%1,%2,%3}, {%4,%5,%6,%7}, {%8,%9}, {%0,%1,%2,%3};"
        : "+f"(d0), "+f"(d1), "+f"(d2), "+f"(d3)
        : "r"(a0), "r"(a1), "r"(a2), "r"(a3), "r"(b0), "r"(b1));
}

// ---------------------------------------------------------------------------
// Kernel 1: P[dir][v][q] = bf16x2( (E[v]@Wx+b)[perm q], [perm q + 8] )
// q: block bq=q>>3, gm=q&7 -> o1 = ((q>>3)&1)*256 + 8*(q>>4) + (q&7); o2=o1+128
// ---------------------------------------------------------------------------
__global__ __launch_bounds__(512) void pbuild_kernel(
    const float* __restrict__ E,
    const float* __restrict__ Wx_f, const float* __restrict__ b_f,
    const float* __restrict__ Wx_b, const float* __restrict__ b_b)
{
    int dir = blockIdx.y;
    int r0  = blockIdx.x * PG;
    const float* __restrict__ Wx = dir ? Wx_b : Wx_f;
    const float* __restrict__ bs = dir ? b_b : b_f;

    __shared__ __align__(16) float x_s[EMB][PG];
    __shared__ float ps[PG][ZC];     // fp32 results in ORIGINAL column order
    int tid = threadIdx.x;
    for (int i = tid; i < PG * EMB; i += 512) {
        int r = i & (PG - 1), e = i / PG;
        int row = r0 + r;
        x_s[e][r] = (row < VOCAB) ? E[row * EMB + e] : 0.0f;
    }
    __syncthreads();

    float bv = bs[tid];
    u64 bp = pk2(bv, bv);
    u64 acc[PG / 2];
#pragma unroll
    for (int p = 0; p < PG / 2; p++) acc[p] = bp;

    const float* wc = Wx + tid;
#pragma unroll 4
    for (int e = 0; e < EMB; e++) {
        float w = wc[e * ZC];
        u64 wd = pk2(w, w);
        const u64* xp = (const u64*)&x_s[e][0];
#pragma unroll
        for (int p = 0; p < PG / 2; p++) ffma2(acc[p], wd, xp[p]);
    }
#pragma unroll
    for (int p = 0; p < PG / 2; p++) {
        float lo, hi; upk2(acc[p], lo, hi);
        ps[2 * p][tid] = lo;
        ps[2 * p + 1][tid] = hi;
    }
    __syncthreads();

    for (int i = tid; i < PG * (ZC / 2); i += 512) {
        int r = i >> 8, q = i & 255;
        int o1 = ((q >> 3) & 1) * 256 + 8 * (q >> 4) + (q & 7);
        int row = r0 + r;
        if (row < VOCAB)
            g_P[dir][row][q] = pack_bf16(ps[r][o1], ps[r][o1 + 128]);
    }
}

// ---------------------------------------------------------------------------
// Kernel 2: persistent LSTM. Operand swap: A = Wh^T (m = permuted z-cols, in
// registers), B = h (n = 8 batch rows, k = hidden, in double-buffered smem).
// Full m16n8k16 utilization: 16 HMMA/warp/step. Lane-local epilogue (no shfl).
// 128 blocks = 2 dirs x 64 batch-groups, 512 threads.
// ---------------------------------------------------------------------------
__global__ __launch_bounds__(512, 1) void lstm_kernel(
    const int* __restrict__ inputs,
    const float* __restrict__ Wh_f, const float* __restrict__ Wh_b)
{
    __shared__ __align__(16) u32 hA[512];   // [kc][lane][2] : B-fragment layout
    __shared__ __align__(16) u32 hB[512];
    __shared__ int tok_s[G][LL];

    int dir = blockIdx.x >> 6;
    int bi  = blockIdx.x & 63;
    int b0  = bi * G;
    const float* __restrict__ Wh = dir ? Wh_b : Wh_f;
    int tid  = threadIdx.x;
    int w    = tid >> 5;       // warp: m-cols [32w,32w+32) = gates 0-3 of units [8w,8w+8)
    int lane = tid & 31;
    int gm   = lane >> 2;      // unit offset / A-frag row group
    int tl   = lane & 3;       // k-pair selector / batch pair (n = 2tl, 2tl+1)

    for (int i = tid; i < 512; i += 512) { hA[i] = 0u; hB[i] = 0u; }
    for (int i = tid; i < G * LL; i += 512) {
        int g = i >> 8, t = i & 255;
        tok_s[g][t] = inputs[(b0 + g) * LL + t];
    }

    int u = 8 * w + gm;    // this lane's hidden unit

    // A fragments: Wh rows = k, cols = orig(z-col). tile ti covers gates 2ti, 2ti+1.
    u32 afr[2][8][4];
#pragma unroll
    for (int ti = 0; ti < 2; ti++) {
        int oA = (2 * ti) * 128 + u;      // gate 2ti
        int oB = oA + 128;                // gate 2ti+1
#pragma unroll
        for (int kc = 0; kc < 8; kc++) {
            int kb = 16 * kc + 2 * tl;
            afr[ti][kc][0] = pack_bf16(Wh[kb * ZC + oA],       Wh[(kb + 1) * ZC + oA]);
            afr[ti][kc][1] = pack_bf16(Wh[kb * ZC + oB],       Wh[(kb + 1) * ZC + oB]);
            afr[ti][kc][2] = pack_bf16(Wh[(kb + 8) * ZC + oA], Wh[(kb + 9) * ZC + oA]);
            afr[ti][kc][3] = pack_bf16(Wh[(kb + 8) * ZC + oB], Wh[(kb + 9) * ZC + oB]);
        }
    }
    __syncthreads();

    int be = 2 * tl, bo = be + 1;       // batch rows (local) this lane owns
    int q0 = (2 * w) * 8 + gm, q1 = q0 + 8;

    // h write slots (halfword indices into hb buffer)
    int j = u & 15, kch = u >> 4;
    int rr = (j >> 3) & 1, tlp = (j & 7) >> 1, half = j & 1;
    int hwE = ((kch * 64 + (be * 4 + tlp) * 2 + rr) << 1) + half;
    int hwO = hwE + 16;                 // odd batch: lane' += 4 -> u32 idx += 8

    u32* stage = &g_hstage[dir][bi][0][0];

    int t0 = dir ? (LL - 1) : 0;
    u32 pE0 = g_P[dir][tok_s[be][t0]][q0];
    u32 pE1 = g_P[dir][tok_s[be][t0]][q1];
    u32 pO0 = g_P[dir][tok_s[bo][t0]][q0];
    u32 pO1 = g_P[dir][tok_s[bo][t0]][q1];

    float c0 = 0.0f, c1 = 0.0f;

    for (int step = 0; step < LL; step++) {
        int t = dir ? (LL - 1 - step) : step;
        const u32* rd = (step & 1) ? hB : hA;
        __nv_bfloat16* wrh = (__nv_bfloat16*)((step & 1) ? hA : hB);

        // acc init from P: tile ti d0/d2 = even batch (perm p, p+8); d1/d3 = odd
        float d[2][4];
        {
            float2 v;
            v = unpack_bf16(pE0); d[0][0] = v.x; d[0][2] = v.y;
            v = unpack_bf16(pO0); d[0][1] = v.x; d[0][3] = v.y;
            v = unpack_bf16(pE1); d[1][0] = v.x; d[1][2] = v.y;
            v = unpack_bf16(pO1); d[1][1] = v.x; d[1][3] = v.y;
        }

        int tn = (step + 1 < LL) ? (dir ? t - 1 : t + 1) : t;
        pE0 = g_P[dir][tok_s[be][tn]][q0];
        pE1 = g_P[dir][tok_s[be][tn]][q1];
        pO0 = g_P[dir][tok_s[bo][tn]][q0];
        pO1 = g_P[dir][tok_s[bo][tn]][q1];

#pragma unroll
        for (int kc = 0; kc < 8; kc++) {
            uint2 bb = *(const uint2*)&rd[kc * 64 + lane * 2];
            mma16816(d[0][0], d[0][1], d[0][2], d[0][3],
                     afr[0][kc][0], afr[0][kc][1], afr[0][kc][2], afr[0][kc][3],
                     bb.x, bb.y);
            mma16816(d[1][0], d[1][1], d[1][2], d[1][3],
                     afr[1][kc][0], afr[1][kc][1], afr[1][kc][2], afr[1][kc][3],
                     bb.x, bb.y);
        }

        // lane-local epilogue: i=d[0][0/1], f=d[0][2/3], g=d[1][0/1], o=d[1][2/3]
        c0 = fast_sig(d[0][2]) * c0 + fast_sig(d[0][0]) * fast_tanh(d[1][0]);
        float hE = fast_sig(d[1][2]) * fast_tanh(c0);
        c1 = fast_sig(d[0][3]) * c1 + fast_sig(d[0][1]) * fast_tanh(d[1][1]);
        float hO = fast_sig(d[1][3]) * fast_tanh(c1);

        wrh[hwE] = __float2bfloat16(hE);
        wrh[hwO] = __float2bfloat16(hO);
        stage[t * 512 + tid] = pack_bf16(hE, hO);   // coalesced
        __syncthreads();
    }
}

// ---------------------------------------------------------------------------
// Kernel 3: logits[b][t][k] = hcat[bt] . Wd[:,k] + bd[k]; h gathered from
// g_hstage: tid' = (u>>3)*32 + (u&7)*4 + ((b&7)>>1), half = b&1
// ---------------------------------------------------------------------------
__global__ __launch_bounds__(512) void logits_kernel(
    const float* __restrict__ Wd, const float* __restrict__ bd)
{
    __shared__ __align__(16) float h_s[LR][2 * RNN];
    __shared__ __align__(16) float2 Wt2[KK][RNN + 1];
    __shared__ float bd_s[KK];

    int tid = threadIdx.x;
    int bt0 = blockIdx.x * LR;

    for (int i = tid; i < KK * RNN; i += 512) {
        int k = i / RNN, e2 = i % RNN;
        Wt2[k][e2] = make_float2(Wd[(2 * e2) * KK + k], Wd[(2 * e2 + 1) * KK + k]);
    }
    if (tid < KK) bd_s[tid] = bd[tid];
    for (int i = tid; i < LR * 2 * RNN; i += 512) {
        int r = i >> 8, e = i & 255;
        int bt = bt0 + r;
        if (bt < BB * LL) {
            int b = bt >> 8, t = bt & 255;
            int dir = e >> 7, uu = e & 127;
            u32 v = g_hstage[dir][b >> 3][t][(uu >> 3) * 32 + (uu & 7) * 4 + ((b & 7) >> 1)];
            float2 hv = unpack_bf16(v);
            h_s[r][e] = (b & 1) ? hv.y : hv.x;
        }
    }
    __syncthreads();

    if (tid >= LR * KK) return;
    int r = tid / KK, k = tid % KK;
    int bt = bt0 + r;
    if (bt >= BB * LL) return;

    u64 acc = 0;
    const u64* hp = (const u64*)&h_s[r][0];
    const u64* wp = (const u64*)&Wt2[k][0];
#pragma unroll 8
    for (int e2 = 0; e2 < RNN; e2++) ffma2(acc, hp[e2], wp[e2]);

    float lo, hi; upk2(acc, lo, hi);
    int b = bt >> 8, t = bt & 255;
    g_logits[b][t][k] = lo + hi + bd_s[k];
}

// ---------------------------------------------------------------------------
// Kernel 4: CRF log-likelihood (+ fused T copy). expT trick.
// ---------------------------------------------------------------------------
__global__ __launch_bounds__(128) void crf_kernel(
    const int* __restrict__ labels, const float* __restrict__ T,
    float* __restrict__ out, int out_size)
{
    if (blockIdx.x == BB / 4) {
        for (int i = threadIdx.x; i < KK * KK; i += 128)
            if ((BB + i) < out_size) out[BB + i] = T[i];
        return;
    }

    __shared__ float T_s[KK * KK];
    __shared__ float expT_s[KK][KK];
    int tid = threadIdx.x;
    for (int i = tid; i < KK * KK; i += 128) {
        float tv = T[i];
        T_s[i] = tv;
        expT_s[i / KK][i % KK] = __expf(tv);
    }
    __syncthreads();

    int warp = tid >> 5;
    int lane = tid & 31;
    int b = blockIdx.x * 4 + warp;
    if (b >= BB) return;

    const int* lab = labels + b * LL;

    int cnt = 0;
    for (int l = lane; l < LL; l += 32) cnt += (lab[l] != 0);
#pragma unroll
    for (int off = 16; off; off >>= 1) cnt += __shfl_xor_sync(0xffffffffu, cnt, off);
    int len = cnt;

    float us = 0.0f, bs = 0.0f;
    for (int l = lane; l < LL; l += 32) {
        int y = lab[l];
        if (l < len) us += g_logits[b][l][y];
        if (l >= 1 && l < len) bs += T_s[lab[l - 1] * KK + y];
    }
#pragma unroll
    for (int off = 16; off; off >>= 1) {
        us += __shfl_xor_sync(0xffffffffu, us, off);
        bs += __shfl_xor_sync(0xffffffffu, bs, off);
    }

    int k = (lane < KK) ? lane : 0;
    float alpha = (lane < KK) ? g_logits[b][0][k] : -1e30f;
    for (int l = 1; l < LL; l++) {
        float m = alpha;
#pragma unroll
        for (int off = 16; off; off >>= 1) m = fmaxf(m, __shfl_xor_sync(0xffffffffu, m, off));
        float e = (lane < KK) ? __expf(alpha - m) : 0.0f;
        float s = 0.0f;
#pragma unroll
        for (int k1 = 0; k1 < KK; k1++)
            s = fmaf(__shfl_sync(0xffffffffu, e, k1), expT_s[k1][k], s);
        float na = m + __logf(s) + g_logits[b][l][k];
        if (lane < KK && l < len) alpha = na;
    }

    float m = alpha;
#pragma unroll
    for (int off = 16; off; off >>= 1) m = fmaxf(m, __shfl_xor_sync(0xffffffffu, m, off));
    float es = (lane < KK) ? __expf(alpha - m) : 0.0f;
#pragma unroll
    for (int off = 16; off; off >>= 1) es += __shfl_xor_sync(0xffffffffu, es, off);
    float lse = m + __logf(es);

    if (lane == 0 && b < out_size) out[b] = us + bs - lse;
}

// ---------------------------------------------------------------------------
extern "C" void kernel_launch(void* const* d_in, const int* in_sizes, int n_in,
                              void* d_out, int out_size)
{
    const int*   inputs = (const int*)  d_in[0];
    const int*   labels = (const int*)  d_in[1];
    const float* E      = (const float*)d_in[2];
    const float* Wx_f   = (const float*)d_in[3];
    const float* Wh_f   = (const float*)d_in[4];
    const float* b_f    = (const float*)d_in[5];
    const float* Wx_b   = (const float*)d_in[6];
    const float* Wh_b   = (const float*)d_in[7];
    const float* b_b    = (const float*)d_in[8];
    const float* Wd     = (const float*)d_in[9];
    const float* bd     = (const float*)d_in[10];
    const float* T      = (const float*)d_in[11];
    float* out = (float*)d_out;

    dim3 pg((VOCAB + PG - 1) / PG, 2);
    pbuild_kernel<<<pg, 512>>>(E, Wx_f, b_f, Wx_b, b_b);
    lstm_kernel<<<128, 512>>>(inputs, Wh_f, Wh_b);
    int nbt = BB * LL;
    logits_kernel<<<(nbt + LR - 1) / LR, 512>>>(Wd, bd);
    crf_kernel<<<BB / 4 + 1, 128>>>(labels, T, out, out_size);
}

// round 9
// speedup vs baseline: 1.4187x; 1.0213x over previous
#include <cuda_runtime.h>
#include <cuda_bf16.h>
#include <math.h>

#define EMB 64
#define RNN 128
#define BB  512
#define LL  256
#define KK  18
#define G   8
#define ZC  512   // 4*RNN
#define VOCAB 30001
#define PG  16    // vocab rows per pbuild block
#define LR  28    // (b,t) rows per logits block

// Scratch (static device allocations; no cudaMalloc allowed)
// g_P2[dir][v][u] = {bf16x2(z_i, z_f), bf16x2(z_g, z_o)} for hidden unit u
__device__ uint2 g_P2[2][VOCAB][RNN];                 // ~61 MB (L2-resident)
// h staging: [dir][batch-group][t][tid] = bf16x2(h_even_batch, h_odd_batch)
__device__ unsigned int g_hstage[2][BB / G][LL][512]; // 67 MB, coalesced writes
__device__ float g_logits[BB][LL][KK];

typedef unsigned long long u64;
typedef unsigned int u32;

__device__ __forceinline__ u64 pk2(float lo, float hi) {
    u64 r; asm("mov.b64 %0,{%1,%2};" : "=l"(r) : "f"(lo), "f"(hi)); return r;
}
__device__ __forceinline__ void upk2(u64 v, float& lo, float& hi) {
    asm("mov.b64 {%0,%1},%2;" : "=f"(lo), "=f"(hi) : "l"(v));
}
__device__ __forceinline__ void ffma2(u64& d, u64 a, u64 b) {
    asm("fma.rn.f32x2 %0,%1,%2,%0;" : "+l"(d) : "l"(a), "l"(b));
}
__device__ __forceinline__ float fast_tanh(float x) {
    float y; asm("tanh.approx.f32 %0, %1;" : "=f"(y) : "f"(x)); return y;
}
__device__ __forceinline__ float fast_sig(float x) {
    return 0.5f * fast_tanh(0.5f * x) + 0.5f;
}
__device__ __forceinline__ u32 pack_bf16(float lo, float hi) {
    __nv_bfloat162 v = __floats2bfloat162_rn(lo, hi);
    return *(u32*)&v;
}
__device__ __forceinline__ float2 unpack_bf16(u32 v) {
    __nv_bfloat162 b = *(__nv_bfloat162*)&v;
    return make_float2(__bfloat162float(b.x), __bfloat162float(b.y));
}
__device__ __forceinline__ void mma16816(float& d0, float& d1, float& d2, float& d3,
                                         u32 a0, u32 a1, u32 a2, u32 a3,
                                         u32 b0, u32 b1) {
    asm("mma.sync.aligned.m16n8k16.row.col.f32.bf16.bf16.f32 "
        "{%0,%1,%2,%3}, {%4,%5,%6,%7}, {%8,%9}, {%0,%1,%2,%3};"
        : "+f"(d0), "+f"(d1), "+f"(d2), "+f"(d3)
        : "r"(a0), "r"(a1), "r"(a2), "r"(a3), "r"(b0), "r"(b1));
}

// ---------------------------------------------------------------------------
// Kernel 1: P2[dir][v][u] = bf16-packed 4 gates of unit u of E[v]@Wx + b
// ---------------------------------------------------------------------------
__global__ __launch_bounds__(512) void pbuild_kernel(
    const float* __restrict__ E,
    const float* __restrict__ Wx_f, const float* __restrict__ b_f,
    const float* __restrict__ Wx_b, const float* __restrict__ b_b)
{
    int dir = blockIdx.y;
    int r0  = blockIdx.x * PG;
    const float* __restrict__ Wx = dir ? Wx_b : Wx_f;
    const float* __restrict__ bs = dir ? b_b : b_f;

    __shared__ __align__(16) float x_s[EMB][PG];
    __shared__ float ps[PG][ZC];     // fp32 results in ORIGINAL column order
    int tid = threadIdx.x;
    for (int i = tid; i < PG * EMB; i += 512) {
        int r = i & (PG - 1), e = i / PG;
        int row = r0 + r;
        x_s[e][r] = (row < VOCAB) ? E[row * EMB + e] : 0.0f;
    }
    __syncthreads();

    float bv = bs[tid];
    u64 bp = pk2(bv, bv);
    u64 acc[PG / 2];
#pragma unroll
    for (int p = 0; p < PG / 2; p++) acc[p] = bp;

    const float* wc = Wx + tid;
#pragma unroll 4
    for (int e = 0; e < EMB; e++) {
        float w = wc[e * ZC];
        u64 wd = pk2(w, w);
        const u64* xp = (const u64*)&x_s[e][0];
#pragma unroll
        for (int p = 0; p < PG / 2; p++) ffma2(acc[p], wd, xp[p]);
    }
#pragma unroll
    for (int p = 0; p < PG / 2; p++) {
        float lo, hi; upk2(acc[p], lo, hi);
        ps[2 * p][tid] = lo;
        ps[2 * p + 1][tid] = hi;
    }
    __syncthreads();

    for (int i = tid; i < PG * RNN; i += 512) {
        int r = i >> 7, u = i & 127;
        int row = r0 + r;
        if (row < VOCAB)
            g_P2[dir][row][u] = make_uint2(
                pack_bf16(ps[r][u],       ps[r][u + 128]),
                pack_bf16(ps[r][u + 256], ps[r][u + 384]));
    }
}

// ---------------------------------------------------------------------------
// Kernel 2: persistent LSTM. A = Wh^T (registers), B = h (smem, n=8 batch).
// 4 independent HMMA chains per warp (kc split), LDG.64 P gather, 1 bar/step.
// ---------------------------------------------------------------------------
__global__ __launch_bounds__(512, 1) void lstm_kernel(
    const int* __restrict__ inputs,
    const float* __restrict__ Wh_f, const float* __restrict__ Wh_b)
{
    __shared__ __align__(16) u32 hA[512];   // B-fragment layout, double-buffered
    __shared__ __align__(16) u32 hB[512];
    __shared__ __align__(8) int2 tok2_s[LL][4];   // {tok[2tl], tok[2tl+1]} per t

    int dir = blockIdx.x >> 6;
    int bi  = blockIdx.x & 63;
    int b0  = bi * G;
    const float* __restrict__ Wh = dir ? Wh_b : Wh_f;
    int tid  = threadIdx.x;
    int w    = tid >> 5;
    int lane = tid & 31;
    int gm   = lane >> 2;      // unit offset within warp
    int tl   = lane & 3;       // k-pair selector / batch pair (n = 2tl, 2tl+1)

    for (int i = tid; i < 512; i += 512) { hA[i] = 0u; hB[i] = 0u; }
    for (int i = tid; i < 4 * LL; i += 512) {
        int t = i >> 2, pr = i & 3;
        tok2_s[t][pr] = make_int2(inputs[(b0 + 2 * pr) * LL + t],
                                  inputs[(b0 + 2 * pr + 1) * LL + t]);
    }

    int u = 8 * w + gm;        // this lane's hidden unit

    // A fragments: tile ti covers gates 2ti, 2ti+1 of the warp's 8 units
    u32 afr[2][8][4];
#pragma unroll
    for (int ti = 0; ti < 2; ti++) {
        int oA = (2 * ti) * 128 + u;
        int oB = oA + 128;
#pragma unroll
        for (int kc = 0; kc < 8; kc++) {
            int kb = 16 * kc + 2 * tl;
            afr[ti][kc][0] = pack_bf16(Wh[kb * ZC + oA],       Wh[(kb + 1) * ZC + oA]);
            afr[ti][kc][1] = pack_bf16(Wh[kb * ZC + oB],       Wh[(kb + 1) * ZC + oB]);
            afr[ti][kc][2] = pack_bf16(Wh[(kb + 8) * ZC + oA], Wh[(kb + 9) * ZC + oA]);
            afr[ti][kc][3] = pack_bf16(Wh[(kb + 8) * ZC + oB], Wh[(kb + 9) * ZC + oB]);
        }
    }
    __syncthreads();

    // h write slots (halfword indices into write buffer)
    int be = 2 * tl;
    int j = u & 15, kch = u >> 4;
    int rr = (j >> 3) & 1, tlp = (j & 7) >> 1, half = j & 1;
    int hwE = ((kch * 64 + (be * 4 + tlp) * 2 + rr) << 1) + half;
    int hwO = hwE + 16;

    u32* stage = &g_hstage[dir][bi][0][0];

    int t0 = dir ? (LL - 1) : 0;
    int2 tk = tok2_s[t0][tl];
    uint2 pE = g_P2[dir][tk.x][u];
    uint2 pO = g_P2[dir][tk.y][u];

    float c0 = 0.0f, c1 = 0.0f;

    for (int step = 0; step < LL; step++) {
        int t = dir ? (LL - 1 - step) : step;
        const u32* rd = (step & 1) ? hB : hA;
        __nv_bfloat16* wrh = (__nv_bfloat16*)((step & 1) ? hA : hB);

        // acc init from P: chain A gets P, chain B starts at 0
        float dA[2][4], dB[2][4];
        {
            float2 v;
            v = unpack_bf16(pE.x); dA[0][0] = v.x; dA[0][2] = v.y;
            v = unpack_bf16(pO.x); dA[0][1] = v.x; dA[0][3] = v.y;
            v = unpack_bf16(pE.y); dA[1][0] = v.x; dA[1][2] = v.y;
            v = unpack_bf16(pO.y); dA[1][1] = v.x; dA[1][3] = v.y;
#pragma unroll
            for (int ti = 0; ti < 2; ti++)
#pragma unroll
                for (int r = 0; r < 4; r++) dB[ti][r] = 0.0f;
        }

        // prefetch next step's P rows (hidden behind MMA loop)
        int tn = (step + 1 < LL) ? (dir ? t - 1 : t + 1) : t;
        tk = tok2_s[tn][tl];
        pE = g_P2[dir][tk.x][u];
        pO = g_P2[dir][tk.y][u];

        // 4 independent HMMA chains: (tile0,kc0-3), (tile1,kc0-3), (tile0,kc4-7), (tile1,kc4-7)
#pragma unroll
        for (int kc = 0; kc < 4; kc++) {
            uint2 bb = *(const uint2*)&rd[kc * 64 + lane * 2];
            mma16816(dA[0][0], dA[0][1], dA[0][2], dA[0][3],
                     afr[0][kc][0], afr[0][kc][1], afr[0][kc][2], afr[0][kc][3],
                     bb.x, bb.y);
            mma16816(dA[1][0], dA[1][1], dA[1][2], dA[1][3],
                     afr[1][kc][0], afr[1][kc][1], afr[1][kc][2], afr[1][kc][3],
                     bb.x, bb.y);
            uint2 bb2 = *(const uint2*)&rd[(kc + 4) * 64 + lane * 2];
            mma16816(dB[0][0], dB[0][1], dB[0][2], dB[0][3],
                     afr[0][kc + 4][0], afr[0][kc + 4][1], afr[0][kc + 4][2], afr[0][kc + 4][3],
                     bb2.x, bb2.y);
            mma16816(dB[1][0], dB[1][1], dB[1][2], dB[1][3],
                     afr[1][kc + 4][0], afr[1][kc + 4][1], afr[1][kc + 4][2], afr[1][kc + 4][3],
                     bb2.x, bb2.y);
        }

        float zi0 = dA[0][0] + dB[0][0], zi1 = dA[0][1] + dB[0][1];
        float zf0 = dA[0][2] + dB[0][2], zf1 = dA[0][3] + dB[0][3];
        float zg0 = dA[1][0] + dB[1][0], zg1 = dA[1][1] + dB[1][1];
        float zo0 = dA[1][2] + dB[1][2], zo1 = dA[1][3] + dB[1][3];

        c0 = fast_sig(zf0) * c0 + fast_sig(zi0) * fast_tanh(zg0);
        float hE = fast_sig(zo0) * fast_tanh(c0);
        c1 = fast_sig(zf1) * c1 + fast_sig(zi1) * fast_tanh(zg1);
        float hO = fast_sig(zo1) * fast_tanh(c1);

        wrh[hwE] = __float2bfloat16(hE);
        wrh[hwO] = __float2bfloat16(hO);
        stage[t * 512 + tid] = pack_bf16(hE, hO);   // coalesced
        __syncthreads();
    }
}

// ---------------------------------------------------------------------------
// Kernel 3: logits[b][t][k] = hcat[bt] . Wd[:,k] + bd[k]; h from g_hstage
// ---------------------------------------------------------------------------
__global__ __launch_bounds__(512) void logits_kernel(
    const float* __restrict__ Wd, const float* __restrict__ bd)
{
    __shared__ __align__(16) float h_s[LR][2 * RNN];
    __shared__ __align__(16) float2 Wt2[KK][RNN + 1];
    __shared__ float bd_s[KK];

    int tid = threadIdx.x;
    int bt0 = blockIdx.x * LR;

    for (int i = tid; i < KK * RNN; i += 512) {
        int k = i / RNN, e2 = i % RNN;
        Wt2[k][e2] = make_float2(Wd[(2 * e2) * KK + k], Wd[(2 * e2 + 1) * KK + k]);
    }
    if (tid < KK) bd_s[tid] = bd[tid];
    for (int i = tid; i < LR * 2 * RNN; i += 512) {
        int r = i >> 8, e = i & 255;
        int bt = bt0 + r;
        if (bt < BB * LL) {
            int b = bt >> 8, t = bt & 255;
            int dir = e >> 7, uu = e & 127;
            u32 v = g_hstage[dir][b >> 3][t][(uu >> 3) * 32 + (uu & 7) * 4 + ((b & 7) >> 1)];
            float2 hv = unpack_bf16(v);
            h_s[r][e] = (b & 1) ? hv.y : hv.x;
        }
    }
    __syncthreads();

    if (tid >= LR * KK) return;
    int r = tid / KK, k = tid % KK;
    int bt = bt0 + r;
    if (bt >= BB * LL) return;

    u64 acc = 0;
    const u64* hp = (const u64*)&h_s[r][0];
    const u64* wp = (const u64*)&Wt2[k][0];
#pragma unroll 8
    for (int e2 = 0; e2 < RNN; e2++) ffma2(acc, hp[e2], wp[e2]);

    float lo, hi; upk2(acc, lo, hi);
    int b = bt >> 8, t = bt & 255;
    g_logits[b][t][k] = lo + hi + bd_s[k];
}

// ---------------------------------------------------------------------------
// Kernel 4: CRF log-likelihood (+ fused T copy). expT trick + logit prefetch
// + lane-0 shift instead of per-step max reduction (alphas stay tight:
// T in [0,1], logits small -> shift by alpha_0 is numerically safe).
// ---------------------------------------------------------------------------
__global__ __launch_bounds__(128) void crf_kernel(
    const int* __restrict__ labels, const float* __restrict__ T,
    float* __restrict__ out, int out_size)
{
    if (blockIdx.x == BB / 4) {
        for (int i = threadIdx.x; i < KK * KK; i += 128)
            if ((BB + i) < out_size) out[BB + i] = T[i];
        return;
    }

    __shared__ float T_s[KK * KK];
    __shared__ float expT_s[KK][KK];
    int tid = threadIdx.x;
    for (int i = tid; i < KK * KK; i += 128) {
        float tv = T[i];
        T_s[i] = tv;
        expT_s[i / KK][i % KK] = __expf(tv);
    }
    __syncthreads();

    int warp = tid >> 5;
    int lane = tid & 31;
    int b = blockIdx.x * 4 + warp;
    if (b >= BB) return;

    const int* lab = labels + b * LL;

    int cnt = 0;
    for (int l = lane; l < LL; l += 32) cnt += (lab[l] != 0);
#pragma unroll
    for (int off = 16; off; off >>= 1) cnt += __shfl_xor_sync(0xffffffffu, cnt, off);
    int len = cnt;

    float us = 0.0f, bs = 0.0f;
    for (int l = lane; l < LL; l += 32) {
        int y = lab[l];
        if (l < len) us += g_logits[b][l][y];
        if (l >= 1 && l < len) bs += T_s[lab[l - 1] * KK + y];
    }
#pragma unroll
    for (int off = 16; off; off >>= 1) {
        us += __shfl_xor_sync(0xffffffffu, us, off);
        bs += __shfl_xor_sync(0xffffffffu, bs, off);
    }

    int k = (lane < KK) ? lane : 0;
    float alpha = (lane < KK) ? g_logits[b][0][k] : -1e30f;
    float lg = g_logits[b][1][k];        // prefetched logit row
    for (int l = 1; l < LL; l++) {
        float lg_next = (l + 1 < LL) ? g_logits[b][l + 1][k] : 0.0f;
        float a0 = __shfl_sync(0xffffffffu, alpha, 0);
        float e = (lane < KK) ? __expf(alpha - a0) : 0.0f;
        float s = 0.0f;
#pragma unroll
        for (int k1 = 0; k1 < KK; k1++)
            s = fmaf(__shfl_sync(0xffffffffu, e, k1), expT_s[k1][k], s);
        float na = a0 + __logf(s) + lg;
        if (lane < KK && l < len) alpha = na;
        lg = lg_next;
    }

    float m = alpha;
#pragma unroll
    for (int off = 16; off; off >>= 1) m = fmaxf(m, __shfl_xor_sync(0xffffffffu, m, off));
    float es = (lane < KK) ? __expf(alpha - m) : 0.0f;
#pragma unroll
    for (int off = 16; off; off >>= 1) es += __shfl_xor_sync(0xffffffffu, es, off);
    float lse = m + __logf(es);

    if (lane == 0 && b < out_size) out[b] = us + bs - lse;
}

// ---------------------------------------------------------------------------
extern "C" void kernel_launch(void* const* d_in, const int* in_sizes, int n_in,
                              void* d_out, int out_size)
{
    const int*   inputs = (const int*)  d_in[0];
    const int*   labels = (const int*)  d_in[1];
    const float* E      = (const float*)d_in[2];
    const float* Wx_f   = (const float*)d_in[3];
    const float* Wh_f   = (const float*)d_in[4];
    const float* b_f    = (const float*)d_in[5];
    const float* Wx_b   = (const float*)d_in[6];
    const float* Wh_b   = (const float*)d_in[7];
    const float* b_b    = (const float*)d_in[8];
    const float* Wd     = (const float*)d_in[9];
    const float* bd     = (const float*)d_in[10];
    const float* T      = (const float*)d_in[11];
    float* out = (float*)d_out;

    dim3 pg((VOCAB + PG - 1) / PG, 2);
    pbuild_kernel<<<pg, 512>>>(E, Wx_f, b_f, Wx_b, b_b);
    lstm_kernel<<<128, 512>>>(inputs, Wh_f, Wh_b);
    int nbt = BB * LL;
    logits_kernel<<<(nbt + LR - 1) / LR, 512>>>(Wd, bd);
    crf_kernel<<<BB / 4 + 1, 128>>>(labels, T, out, out_size);
}